// round 3
// baseline (speedup 1.0000x reference)
#include <cuda_runtime.h>

typedef unsigned long long ULL;

// ---------------- device scratch (no allocations allowed) ----------------
// Packed, zero-padded weights: Wpad[lp][c] = (Win_real[c][lp-9], Win_imag[c][lp-9]),
// zero outside l in [0, 4086]. lp in [0, 4105).
__device__ __align__(16) float2 wpad_g[4105 * 16];
// Stage-1 partial sums: [b][s][c][w][2]  (b:256, s:16, c:16, w:10)
__device__ float fpart_g[256 * 16 * 320];
// Pre-batchnorm output: [b][c*2+o]
__device__ float out_g[256 * 32];
// completion counter for last-block BN
__device__ int done_ctr;

// ---------------- packed f32x2 FMA (FFMA2) ----------------
__device__ __forceinline__ ULL fma2(ULL a, ULL b, ULL c) {
    ULL d;
    asm("fma.rn.f32x2 %0, %1, %2, %3;" : "=l"(d) : "l"(a), "l"(b), "l"(c));
    return d;
}

// ---------------- kernel 0: pack + pad weights, reset counter ----------------
__global__ void pack_kernel(const float* __restrict__ wr, const float* __restrict__ wi) {
    int idx = blockIdx.x * blockDim.x + threadIdx.x;
    if (idx == 0) done_ctr = 0;
    if (idx >= 4105 * 16) return;
    int lp = idx >> 4;
    int c  = idx & 15;
    int l  = lp - 9;
    float2 v = make_float2(0.f, 0.f);
    if (l >= 0 && l < 4087) {
        v.x = wr[c * 4087 + l];
        v.y = wi[c * 4087 + l];
    }
    wpad_g[lp * 16 + c] = v;
}

// ---------------- kernel 1: depthwise sliding filters (stage 1) ----------------
// grid (128 batch-pairs, 16 segments), block 256 = 16 channels x 16 n-chunks.
// Weights for the segment staged through smem; each thread walks 16 positions
// for TWO batches with a rotating 10-deep register weight window.
__global__ void __launch_bounds__(256, 2) stage1_kernel(const float* __restrict__ x) {
    __shared__ __align__(16) char smem_raw[33920];    // 265*16*8
    ULL* ws = (ULL*)smem_raw;                          // [265][16]
    float (*red)[322] = (float (*)[322])smem_raw;      // alias after compute (20608B)

    int bp  = blockIdx.x;
    int s   = blockIdx.y;
    int tid = threadIdx.x;
    int c   = tid & 15;
    int j   = tid >> 4;
    int pl  = j * 16;               // local position start
    int ps  = s * 256 + pl;         // global position start
    int b0  = bp * 2;

    // cooperative weight slice load: Wpad[s*256 .. s*256+264], 2120 float4
    {
        const float4* src = (const float4*)(wpad_g + (size_t)s * 256 * 16);
        float4* dst = (float4*)smem_raw;
        for (int i = tid; i < 2120; i += 256) dst[i] = src[i];
    }
    __syncthreads();

    const ULL* xp0 = (const ULL*)x + ((size_t)b0 * 4096 + ps) * 16 + c;
    const ULL* xp1 = xp0 + (size_t)4096 * 16;

    // slot m holds weights; preload local indices pl..pl+8
    ULL wbuf[10];
#pragma unroll
    for (int k = 0; k < 9; k++) wbuf[k] = ws[(pl + k) * 16 + c];

    ULL a0[10], a1[10];
#pragma unroll
    for (int w = 0; w < 10; w++) { a0[w] = 0ULL; a1[w] = 0ULL; }

#pragma unroll
    for (int t = 0; t < 16; t++) {
        ULL xv0 = xp0[(size_t)t * 16];
        ULL xv1 = xp1[(size_t)t * 16];
        wbuf[(t + 9) % 10] = ws[(pl + t + 9) * 16 + c];   // local idx pl+t+9 <= 264
#pragma unroll
        for (int w = 0; w < 10; w++) {
            ULL wv = wbuf[(t + 9 - w) % 10];              // Wpad[p - w + 9]
            a0[w] = fma2(xv0, wv, a0[w]);
            a1[w] = fma2(xv1, wv, a1[w]);
        }
    }
    __syncthreads();    // everyone done reading ws; smem reused as red

    // ---- reduce + store batch 0 ----
#pragma unroll
    for (int w = 0; w < 10; w++) {
        red[j][(c * 10 + w) * 2 + 0] = __uint_as_float((unsigned)(a0[w] & 0xffffffffULL));
        red[j][(c * 10 + w) * 2 + 1] = __uint_as_float((unsigned)(a0[w] >> 32));
    }
    __syncthreads();
    for (int idx = tid; idx < 320; idx += 256) {
        float v = 0.f;
#pragma unroll
        for (int jj = 0; jj < 16; jj++) v += red[jj][idx];
        fpart_g[((size_t)b0 * 16 + s) * 320 + idx] = v;
    }
    __syncthreads();

    // ---- reduce + store batch 1 ----
#pragma unroll
    for (int w = 0; w < 10; w++) {
        red[j][(c * 10 + w) * 2 + 0] = __uint_as_float((unsigned)(a1[w] & 0xffffffffULL));
        red[j][(c * 10 + w) * 2 + 1] = __uint_as_float((unsigned)(a1[w] >> 32));
    }
    __syncthreads();
    for (int idx = tid; idx < 320; idx += 256) {
        float v = 0.f;
#pragma unroll
        for (int jj = 0; jj < 16; jj++) v += red[jj][idx];
        fpart_g[((size_t)(b0 + 1) * 16 + s) * 320 + idx] = v;
    }
}

// ---------------- kernel 2: amp + Linear(2C->2) + out filter + fused BN ----------------
// one block per b, 320 threads; last block to finish runs BatchNorm for all.
__global__ void __launch_bounds__(320) stage23_kernel(const float* __restrict__ Wnl,
                                                      const float* __restrict__ WoR,
                                                      const float* __restrict__ WoI,
                                                      const float* __restrict__ gamma,
                                                      const float* __restrict__ beta,
                                                      float* __restrict__ out) {
    __shared__ float tf[10][32];       // [w][i], i<16: amp*fr, i>=16: amp*fi
    __shared__ float contrib[10][32];  // [w][c*2+o]
    __shared__ int   lastflag;
    __shared__ float wred[10];
    __shared__ float bstat;

    int b = blockIdx.x;
    int tid = threadIdx.x;

    if (tid < 160) {
        int w = tid / 16;
        int c = tid & 15;
        float fr = 0.f, fi = 0.f;
#pragma unroll
        for (int s = 0; s < 16; s++) {
            const float* fp = fpart_g + ((size_t)b * 16 + s) * 320 + (c * 10 + w) * 2;
            fr += fp[0];
            fi += fp[1];
        }
        float amp = fr * fr + fi * fi;
        tf[w][c]      = amp * fr;
        tf[w][16 + c] = amp * fi;
    }
    __syncthreads();

    {
        int w = tid >> 5;
        int q = tid & 31;
        int c = q >> 1;
        int o = q & 1;
        float acc = 0.f;
        const float* wn = Wnl + (c * 2 + o) * 32;
#pragma unroll
        for (int i = 0; i < 32; i++) acc += tf[w][i] * wn[i];
        float wo = (o == 0 ? WoR : WoI)[c * 10 + w];
        contrib[w][q] = acc * wo;
    }
    __syncthreads();

    if (tid < 32) {
        float ssum = 0.f;
#pragma unroll
        for (int ww = 0; ww < 10; ww++) ssum += contrib[ww][tid];
        out_g[b * 32 + tid] = ssum;
    }
    __threadfence();
    __syncthreads();
    if (tid == 0) lastflag = (atomicAdd(&done_ctr, 1) == 255);
    __syncthreads();
    if (!lastflag) return;

    // ----- BatchNorm (training stats) by the last block, 320 threads = 10 warps -----
    int warp = tid >> 5, lane = tid & 31;
    for (int ch = 0; ch < 16; ch++) {
        // pass 1: mean
        float s1 = 0.f;
        for (int idx = tid; idx < 512; idx += 320) {
            float v = __ldcg(&out_g[(idx >> 1) * 32 + ch * 2 + (idx & 1)]);
            s1 += v;
        }
#pragma unroll
        for (int off = 16; off; off >>= 1) s1 += __shfl_xor_sync(0xffffffffu, s1, off);
        if (lane == 0) wred[warp] = s1;
        __syncthreads();
        if (tid == 0) {
            float t1 = 0.f;
#pragma unroll
            for (int k = 0; k < 10; k++) t1 += wred[k];
            bstat = t1 * (1.f / 512.f);
        }
        __syncthreads();
        float mean = bstat;
        __syncthreads();

        // pass 2: variance of centered values
        float s2 = 0.f;
        for (int idx = tid; idx < 512; idx += 320) {
            float v = __ldcg(&out_g[(idx >> 1) * 32 + ch * 2 + (idx & 1)]) - mean;
            s2 += v * v;
        }
#pragma unroll
        for (int off = 16; off; off >>= 1) s2 += __shfl_xor_sync(0xffffffffu, s2, off);
        if (lane == 0) wred[warp] = s2;
        __syncthreads();
        if (tid == 0) {
            float t2 = 0.f;
#pragma unroll
            for (int k = 0; k < 10; k++) t2 += wred[k];
            bstat = rsqrtf(t2 * (1.f / 512.f) + 1e-5f);
        }
        __syncthreads();
        float inv = bstat;
        float g = gamma[ch], bb = beta[ch];
        for (int idx = tid; idx < 512; idx += 320) {
            int off = (idx >> 1) * 32 + ch * 2 + (idx & 1);
            float v = __ldcg(&out_g[off]) - mean;
            out[off] = v * inv * g + bb;
        }
        __syncthreads();
    }
}

// ---------------- launch ----------------
extern "C" void kernel_launch(void* const* d_in, const int* in_sizes, int n_in,
                              void* d_out, int out_size) {
    const float* x     = (const float*)d_in[0];
    const float* wir   = (const float*)d_in[1];
    const float* wii   = (const float*)d_in[2];
    const float* wnl   = (const float*)d_in[3];
    const float* wor   = (const float*)d_in[4];
    const float* woi   = (const float*)d_in[5];
    const float* gamma = (const float*)d_in[6];
    const float* beta  = (const float*)d_in[7];
    float* out = (float*)d_out;

    pack_kernel<<<(4105 * 16 + 255) / 256, 256>>>(wir, wii);
    stage1_kernel<<<dim3(128, 16), 256>>>(x);
    stage23_kernel<<<256, 320>>>(wnl, wor, woi, gamma, beta, out);
}

// round 4
// speedup vs baseline: 1.0254x; 1.0254x over previous
#include <cuda_runtime.h>

typedef unsigned long long ULL;

// ---------------- device scratch (no allocations allowed) ----------------
// Stage-1 partial sums: [b][s][c][w][2]  (b:256, s:32, c:16, w:10)
__device__ float fpart_g[256 * 32 * 320];
// Pre-batchnorm output: [b][c*2+o]
__device__ float out_g[256 * 32];
// completion counter for last-block BN (zero-init; last block re-zeros it)
__device__ int done_ctr;

// ---------------- packed f32x2 FMA (FFMA2) ----------------
__device__ __forceinline__ ULL fma2(ULL a, ULL b, ULL c) {
    ULL d;
    asm("fma.rn.f32x2 %0, %1, %2, %3;" : "=l"(d) : "l"(a), "l"(b), "l"(c));
    return d;
}
__device__ __forceinline__ float2 u2f2(ULL v) {
    return make_float2(__uint_as_float((unsigned)(v & 0xffffffffULL)),
                       __uint_as_float((unsigned)(v >> 32)));
}

// ---------------- kernel 1: depthwise sliding filters (stage 1) ----------------
// grid (16 batch-groups, 32 segments), 256 threads = 16 channels x 16 batches.
// Each thread: ONE (batch, channel), walks 128 positions with a 10-deep
// rotating register weight window fed from a smem weight slice.
// f[b,w,c] = sum_p x[b,p,c] * Wpad[p - w + 9],  Wpad[lp] = W[lp-9] (zero-padded)
__global__ void __launch_bounds__(256) stage1_kernel(const float* __restrict__ x,
                                                     const float* __restrict__ wr,
                                                     const float* __restrict__ wi) {
    __shared__ __align__(16) ULL ws[137 * 16];   // [i][c]: Wpad[ps+i] for channel c

    int bg  = blockIdx.x;          // 0..15
    int s   = blockIdx.y;          // 0..31
    int tid = threadIdx.x;
    int c   = tid & 15;
    int bl  = tid >> 4;
    int ps  = s * 128;

    // cooperative weight gather with zero-pad: ws[i*16+cc] = {wr[cc][l], wi[cc][l]},
    // l = ps + i - 9. Threads: cc = tid>>4, i strided by it = tid&15 (contiguous l per cc).
    {
        int cc = tid >> 4;
        for (int i = tid & 15; i < 137; i += 16) {
            int l = ps + i - 9;
            float a = 0.f, b = 0.f;
            if (l >= 0 && l < 4087) {
                a = wr[cc * 4087 + l];
                b = wi[cc * 4087 + l];
            }
            float2 v = make_float2(a, b);
            ws[i * 16 + cc] = *(ULL*)&v;
        }
    }
    __syncthreads();

    int b = bg * 16 + bl;
    const ULL* xp = (const ULL*)x + ((size_t)b * 4096 + ps) * 16 + c;

    // rotating window: slot m holds Wpad[ps + lp] with lp % 10 == m
    ULL wbuf[10];
#pragma unroll
    for (int k = 0; k < 9; k++) wbuf[k] = ws[k * 16 + c];

    ULL acc[10];
#pragma unroll
    for (int w = 0; w < 10; w++) acc[w] = 0ULL;

    // main: 12 chunks of 10 positions (static rotation indices), then 8-pos tail
    for (int tt = 0; tt < 12; tt++) {
        int t0 = tt * 10;
#pragma unroll
        for (int u = 0; u < 10; u++) {
            int t = t0 + u;
            ULL xv = xp[(size_t)t * 16];
            wbuf[(u + 9) % 10] = ws[(t + 9) * 16 + c];    // lp = t+9
#pragma unroll
            for (int w = 0; w < 10; w++)
                acc[w] = fma2(xv, wbuf[(u + 9 - w + 10) % 10], acc[w]);
        }
    }
#pragma unroll
    for (int t = 120; t < 128; t++) {
        ULL xv = xp[(size_t)t * 16];
        wbuf[(t + 9) % 10] = ws[(t + 9) * 16 + c];
#pragma unroll
        for (int w = 0; w < 10; w++)
            acc[w] = fma2(xv, wbuf[(t + 9 - w) % 10], acc[w]);
    }

    // direct store: fpart[b][s][(c*10+w)*2 + comp]
    float2* fp = (float2*)(fpart_g + ((size_t)b * 32 + s) * 320) + c * 10;
#pragma unroll
    for (int w = 0; w < 10; w++) fp[w] = u2f2(acc[w]);
}

// ---------------- kernel 2: amp + Linear(2C->2) + out filter + fused BN ----------------
// one block per b, 320 threads; last block to finish runs BatchNorm for all.
__global__ void __launch_bounds__(320) stage23_kernel(const float* __restrict__ Wnl,
                                                      const float* __restrict__ WoR,
                                                      const float* __restrict__ WoI,
                                                      const float* __restrict__ gamma,
                                                      const float* __restrict__ beta,
                                                      float* __restrict__ out) {
    __shared__ float tf[10][32];       // [w][i], i<16: amp*fr, i>=16: amp*fi
    __shared__ float contrib[10][32];  // [w][c*2+o]
    __shared__ int   lastflag;
    __shared__ float wred[10];
    __shared__ float bstat;

    int b = blockIdx.x;
    int tid = threadIdx.x;

    if (tid < 160) {
        int w = tid / 16;
        int c = tid & 15;
        float fr = 0.f, fi = 0.f;
#pragma unroll
        for (int s = 0; s < 32; s++) {
            const float* fp = fpart_g + ((size_t)b * 32 + s) * 320 + (c * 10 + w) * 2;
            fr += fp[0];
            fi += fp[1];
        }
        float amp = fr * fr + fi * fi;
        tf[w][c]      = amp * fr;
        tf[w][16 + c] = amp * fi;
    }
    __syncthreads();

    {
        int w = tid >> 5;
        int q = tid & 31;
        int c = q >> 1;
        int o = q & 1;
        float acc = 0.f;
        const float* wn = Wnl + (c * 2 + o) * 32;
#pragma unroll
        for (int i = 0; i < 32; i++) acc += tf[w][i] * wn[i];
        float wo = (o == 0 ? WoR : WoI)[c * 10 + w];
        contrib[w][q] = acc * wo;
    }
    __syncthreads();

    if (tid < 32) {
        float ssum = 0.f;
#pragma unroll
        for (int ww = 0; ww < 10; ww++) ssum += contrib[ww][tid];
        out_g[b * 32 + tid] = ssum;
    }
    __threadfence();
    __syncthreads();
    if (tid == 0) lastflag = (atomicAdd(&done_ctr, 1) == 255);
    __syncthreads();
    if (!lastflag) return;

    // ----- BatchNorm (training stats) by the last block, 320 threads = 10 warps -----
    int warp = tid >> 5, lane = tid & 31;
    for (int ch = 0; ch < 16; ch++) {
        // pass 1: mean
        float s1 = 0.f;
        for (int idx = tid; idx < 512; idx += 320)
            s1 += __ldcg(&out_g[(idx >> 1) * 32 + ch * 2 + (idx & 1)]);
#pragma unroll
        for (int off = 16; off; off >>= 1) s1 += __shfl_xor_sync(0xffffffffu, s1, off);
        if (lane == 0) wred[warp] = s1;
        __syncthreads();
        if (tid == 0) {
            float t1 = 0.f;
#pragma unroll
            for (int k = 0; k < 10; k++) t1 += wred[k];
            bstat = t1 * (1.f / 512.f);
        }
        __syncthreads();
        float mean = bstat;
        __syncthreads();

        // pass 2: variance of centered values
        float s2 = 0.f;
        for (int idx = tid; idx < 512; idx += 320) {
            float v = __ldcg(&out_g[(idx >> 1) * 32 + ch * 2 + (idx & 1)]) - mean;
            s2 += v * v;
        }
#pragma unroll
        for (int off = 16; off; off >>= 1) s2 += __shfl_xor_sync(0xffffffffu, s2, off);
        if (lane == 0) wred[warp] = s2;
        __syncthreads();
        if (tid == 0) {
            float t2 = 0.f;
#pragma unroll
            for (int k = 0; k < 10; k++) t2 += wred[k];
            bstat = rsqrtf(t2 * (1.f / 512.f) + 1e-5f);
        }
        __syncthreads();
        float inv = bstat;
        float g = gamma[ch], bb = beta[ch];
        for (int idx = tid; idx < 512; idx += 320) {
            int off = (idx >> 1) * 32 + ch * 2 + (idx & 1);
            float v = __ldcg(&out_g[off]) - mean;
            out[off] = v * inv * g + bb;
        }
        __syncthreads();
    }

    // reset for next graph replay (last block, after all work)
    if (tid == 0) done_ctr = 0;
}

// ---------------- launch ----------------
extern "C" void kernel_launch(void* const* d_in, const int* in_sizes, int n_in,
                              void* d_out, int out_size) {
    const float* x     = (const float*)d_in[0];
    const float* wir   = (const float*)d_in[1];
    const float* wii   = (const float*)d_in[2];
    const float* wnl   = (const float*)d_in[3];
    const float* wor   = (const float*)d_in[4];
    const float* woi   = (const float*)d_in[5];
    const float* gamma = (const float*)d_in[6];
    const float* beta  = (const float*)d_in[7];
    float* out = (float*)d_out;

    stage1_kernel<<<dim3(16, 32), 256>>>(x, wir, wii);
    stage23_kernel<<<256, 320>>>(wnl, wor, woi, gamma, beta, out);
}

// round 5
// speedup vs baseline: 1.3937x; 1.3591x over previous
#include <cuda_runtime.h>

typedef unsigned long long ULL;

// ---------------- device scratch (no allocations allowed) ----------------
// Stage-1 partial sums: [b][s][c][w][2]  (b:256, s:32, c:16, w:10)
__device__ float fpart_g[256 * 32 * 320];
// Pre-batchnorm output: [b][c*2+o]
__device__ float out_g[256 * 32];
// completion counter for last-block BN (zero-init; last block re-zeros it)
__device__ int done_ctr;

// ---------------- packed f32x2 FMA (FFMA2) ----------------
__device__ __forceinline__ ULL fma2(ULL a, ULL b, ULL c) {
    ULL d;
    asm("fma.rn.f32x2 %0, %1, %2, %3;" : "=l"(d) : "l"(a), "l"(b), "l"(c));
    return d;
}
__device__ __forceinline__ float2 u2f2(ULL v) {
    return make_float2(__uint_as_float((unsigned)(v & 0xffffffffULL)),
                       __uint_as_float((unsigned)(v >> 32)));
}

// ---------------- kernel 1: depthwise sliding filters (stage 1) ----------------
// grid (16 batch-groups, 32 segments), 256 threads = 16 channels x 16 batches.
// Each thread: ONE (batch, channel), walks 128 positions. Per 10-position chunk
// all 10 x-values are loaded FIRST (MLP~10), then the FMA block runs with a
// 10-deep rotating register weight window fed from a smem weight slice.
// f[b,w,c] = sum_p x[b,p,c] * Wpad[p - w + 9],  Wpad[lp] = W[lp-9] (zero-padded)
__global__ void __launch_bounds__(256) stage1_kernel(const float* __restrict__ x,
                                                     const float* __restrict__ wr,
                                                     const float* __restrict__ wi) {
    __shared__ __align__(16) ULL ws[137 * 16];   // [i][c]: Wpad[ps+i] for channel c

    int bg  = blockIdx.x;          // 0..15
    int s   = blockIdx.y;          // 0..31
    int tid = threadIdx.x;
    int c   = tid & 15;
    int bl  = tid >> 4;
    int ps  = s * 128;

    // cooperative weight gather with zero-pad: ws[i*16+cc] = {wr[cc][l], wi[cc][l]}
    {
        int cc = tid >> 4;
        for (int i = tid & 15; i < 137; i += 16) {
            int l = ps + i - 9;
            float a = 0.f, b = 0.f;
            if (l >= 0 && l < 4087) {
                a = wr[cc * 4087 + l];
                b = wi[cc * 4087 + l];
            }
            float2 v = make_float2(a, b);
            ws[i * 16 + cc] = *(ULL*)&v;
        }
    }
    __syncthreads();

    int b = bg * 16 + bl;
    const ULL* xp = (const ULL*)x + ((size_t)b * 4096 + ps) * 16 + c;

    // rotating window: slot m holds Wpad[ps + lp] with lp % 10 == m
    ULL wbuf[10];
#pragma unroll
    for (int k = 0; k < 9; k++) wbuf[k] = ws[k * 16 + c];

    ULL acc[10];
#pragma unroll
    for (int w = 0; w < 10; w++) acc[w] = 0ULL;

    // main: 12 chunks of 10 positions; x loads batched up front each chunk
    for (int tt = 0; tt < 12; tt++) {
        int t0 = tt * 10;
        ULL xv[10];
#pragma unroll
        for (int u = 0; u < 10; u++) xv[u] = xp[(size_t)(t0 + u) * 16];
#pragma unroll
        for (int u = 0; u < 10; u++) {
            wbuf[(u + 9) % 10] = ws[(t0 + u + 9) * 16 + c];    // lp = t+9
#pragma unroll
            for (int w = 0; w < 10; w++)
                acc[w] = fma2(xv[u], wbuf[(u + 9 - w + 10) % 10], acc[w]);
        }
    }
    // tail: 8 positions, also batched
    {
        ULL xv[8];
#pragma unroll
        for (int u = 0; u < 8; u++) xv[u] = xp[(size_t)(120 + u) * 16];
#pragma unroll
        for (int u = 0; u < 8; u++) {
            int t = 120 + u;
            wbuf[(t + 9) % 10] = ws[(t + 9) * 16 + c];
#pragma unroll
            for (int w = 0; w < 10; w++)
                acc[w] = fma2(xv[u], wbuf[(t + 9 - w) % 10], acc[w]);
        }
    }

    // direct store: fpart[b][s][(c*10+w)*2 + comp]
    float2* fp = (float2*)(fpart_g + ((size_t)b * 32 + s) * 320) + c * 10;
#pragma unroll
    for (int w = 0; w < 10; w++) fp[w] = u2f2(acc[w]);
}

// ---------------- kernel 2: amp + Linear(2C->2) + out filter + fused BN ----------------
// one block per b, 512 threads; last block to finish stages out_g into smem
// (transposed, conflict-free) and runs BatchNorm with one warp per channel.
__global__ void __launch_bounds__(512) stage23_kernel(const float* __restrict__ Wnl,
                                                      const float* __restrict__ WoR,
                                                      const float* __restrict__ WoI,
                                                      const float* __restrict__ gamma,
                                                      const float* __restrict__ beta,
                                                      float* __restrict__ out) {
    __shared__ float tf[10][32];       // [w][i], i<16: amp*fr, i>=16: amp*fi
    __shared__ float contrib[10][32];  // [w][c*2+o]
    __shared__ int   lastflag;
    __shared__ float bnbuf[32][257];   // [q = ch*2+o][b], padded rows

    int b = blockIdx.x;
    int tid = threadIdx.x;

    if (tid < 160) {
        int w = tid / 16;
        int c = tid & 15;
        float fr = 0.f, fi = 0.f;
#pragma unroll
        for (int s = 0; s < 32; s++) {
            const float* fp = fpart_g + ((size_t)b * 32 + s) * 320 + (c * 10 + w) * 2;
            fr += fp[0];
            fi += fp[1];
        }
        float amp = fr * fr + fi * fi;
        tf[w][c]      = amp * fr;
        tf[w][16 + c] = amp * fi;
    }
    __syncthreads();

    if (tid < 320) {
        int w = tid >> 5;
        int q = tid & 31;
        int c = q >> 1;
        int o = q & 1;
        float acc = 0.f;
        const float* wn = Wnl + (c * 2 + o) * 32;
#pragma unroll
        for (int i = 0; i < 32; i++) acc += tf[w][i] * wn[i];
        float wo = (o == 0 ? WoR : WoI)[c * 10 + w];
        contrib[w][q] = acc * wo;
    }
    __syncthreads();

    if (tid < 32) {
        float ssum = 0.f;
#pragma unroll
        for (int ww = 0; ww < 10; ww++) ssum += contrib[ww][tid];
        out_g[b * 32 + tid] = ssum;
    }
    __threadfence();
    __syncthreads();
    if (tid == 0) lastflag = (atomicAdd(&done_ctr, 1) == 255);
    __syncthreads();
    if (!lastflag) return;

    // ----- last block: BatchNorm over (b, o) per channel -----
    // stage out_g (8 KB usable of 32 KB row: 256*32 floats) into smem transposed
    for (int i = tid; i < 8192; i += 512) {
        int bb = i >> 5;
        int q  = i & 31;
        bnbuf[q][bb] = __ldcg(&out_g[i]);
    }
    __syncthreads();

    // one warp per channel: warp ch reduces rows 2ch, 2ch+1 (512 values)
    int ch = tid >> 5, lane = tid & 31;
    {
        float s1 = 0.f;
#pragma unroll
        for (int j = 0; j < 8; j++) {
            int bb = lane + j * 32;
            s1 += bnbuf[2 * ch][bb] + bnbuf[2 * ch + 1][bb];
        }
#pragma unroll
        for (int off = 16; off; off >>= 1) s1 += __shfl_xor_sync(0xffffffffu, s1, off);
        float mean = s1 * (1.f / 512.f);

        float s2 = 0.f;
#pragma unroll
        for (int j = 0; j < 8; j++) {
            int bb = lane + j * 32;
            float d0 = bnbuf[2 * ch][bb] - mean;
            float d1 = bnbuf[2 * ch + 1][bb] - mean;
            s2 += d0 * d0 + d1 * d1;
        }
#pragma unroll
        for (int off = 16; off; off >>= 1) s2 += __shfl_xor_sync(0xffffffffu, s2, off);
        float inv = rsqrtf(s2 * (1.f / 512.f) + 1e-5f);

        float g = gamma[ch], bb_ = beta[ch];
#pragma unroll
        for (int j = 0; j < 8; j++) {
            int bb = lane + j * 32;
            out[bb * 32 + 2 * ch]     = (bnbuf[2 * ch][bb] - mean) * inv * g + bb_;
            out[bb * 32 + 2 * ch + 1] = (bnbuf[2 * ch + 1][bb] - mean) * inv * g + bb_;
        }
    }

    // reset for next graph replay
    if (tid == 0) done_ctr = 0;
}

// ---------------- launch ----------------
extern "C" void kernel_launch(void* const* d_in, const int* in_sizes, int n_in,
                              void* d_out, int out_size) {
    const float* x     = (const float*)d_in[0];
    const float* wir   = (const float*)d_in[1];
    const float* wii   = (const float*)d_in[2];
    const float* wnl   = (const float*)d_in[3];
    const float* wor   = (const float*)d_in[4];
    const float* woi   = (const float*)d_in[5];
    const float* gamma = (const float*)d_in[6];
    const float* beta  = (const float*)d_in[7];
    float* out = (float*)d_out;

    stage1_kernel<<<dim3(16, 32), 256>>>(x, wir, wii);
    stage23_kernel<<<256, 512>>>(wnl, wor, woi, gamma, beta, out);
}

// round 6
// speedup vs baseline: 1.4933x; 1.0715x over previous
#include <cuda_runtime.h>

typedef unsigned long long ULL;

// ---------------- device scratch (no allocations allowed) ----------------
// Stage-1 partial sums: [b][s][idx]  (b:256, s:32, idx:320 = (c*10+w)*2+comp)
__device__ float fpart_g[256 * 32 * 320];
// Pre-batchnorm output: [b][c*2+o]
__device__ float out_g[256 * 32];
// completion counter for last-block BN (zero-init; last block re-zeros it)
__device__ int done_ctr;

// ---------------- packed f32x2 FMA (FFMA2) ----------------
__device__ __forceinline__ ULL fma2(ULL a, ULL b, ULL c) {
    ULL d;
    asm("fma.rn.f32x2 %0, %1, %2, %3;" : "=l"(d) : "l"(a), "l"(b), "l"(c));
    return d;
}
__device__ __forceinline__ float2 u2f2(ULL v) {
    return make_float2(__uint_as_float((unsigned)(v & 0xffffffffULL)),
                       __uint_as_float((unsigned)(v >> 32)));
}

// ---------------- kernel 1: depthwise sliding filters (stage 1) ----------------
// grid (16 batch-groups, 32 segments), 256 threads = 16 channels x 16 batches.
// Each thread: ONE (batch, channel), walks 128 positions, FULLY UNROLLED so
// ptxas can hoist x-loads for high MLP. 10-deep rotating register weight
// window fed from a smem weight slice.
// f[b,w,c] = sum_p x[b,p,c] * Wpad[p - w + 9],  Wpad[lp] = W[lp-9] (zero-padded)
__global__ void __launch_bounds__(256) stage1_kernel(const float* __restrict__ x,
                                                     const float* __restrict__ wr,
                                                     const float* __restrict__ wi) {
    __shared__ __align__(16) ULL ws[137 * 16];   // [i][c]: Wpad[ps+i] for channel c

    int bg  = blockIdx.x;          // 0..15
    int s   = blockIdx.y;          // 0..31
    int tid = threadIdx.x;
    int c   = tid & 15;
    int bl  = tid >> 4;
    int ps  = s * 128;

    // cooperative weight gather with zero-pad: ws[i*16+cc] = {wr[cc][l], wi[cc][l]}
    {
        int cc = tid >> 4;
        for (int i = tid & 15; i < 137; i += 16) {
            int l = ps + i - 9;
            float a = 0.f, b = 0.f;
            if (l >= 0 && l < 4087) {
                a = wr[cc * 4087 + l];
                b = wi[cc * 4087 + l];
            }
            float2 v = make_float2(a, b);
            ws[i * 16 + cc] = *(ULL*)&v;
        }
    }
    __syncthreads();

    int b = bg * 16 + bl;
    const ULL* xp = (const ULL*)x + ((size_t)b * 4096 + ps) * 16 + c;

    // rotating window: slot m holds Wpad[ps + lp] with lp % 10 == m
    ULL wbuf[10];
#pragma unroll
    for (int k = 0; k < 9; k++) wbuf[k] = ws[k * 16 + c];

    ULL acc[10];
#pragma unroll
    for (int w = 0; w < 10; w++) acc[w] = 0ULL;

    // fully unrolled position walk: static rotation indices everywhere;
    // ptxas hoists LDG.64s to its preferred MLP depth.
#pragma unroll
    for (int t = 0; t < 128; t++) {
        ULL xv = xp[(size_t)t * 16];
        wbuf[(t + 9) % 10] = ws[(t + 9) * 16 + c];    // lp = t+9
#pragma unroll
        for (int w = 0; w < 10; w++)
            acc[w] = fma2(xv, wbuf[(t + 9 - w) % 10], acc[w]);
    }

    // store: fpart[b][s][(c*10+w)*2 + comp]
    float2* fp = (float2*)(fpart_g + ((size_t)b * 32 + s) * 320) + c * 10;
#pragma unroll
    for (int w = 0; w < 10; w++) fp[w] = u2f2(acc[w]);
}

// ---------------- kernel 2: amp + Linear(2C->2) + out filter + fused BN ----------------
// one block per b, 512 threads. Phase A: coalesced s-reduction (thread t owns
// flat idx t, shfl pairing for amp). Last block to finish runs BatchNorm.
__global__ void __launch_bounds__(512) stage23_kernel(const float* __restrict__ Wnl,
                                                      const float* __restrict__ WoR,
                                                      const float* __restrict__ WoI,
                                                      const float* __restrict__ gamma,
                                                      const float* __restrict__ beta,
                                                      float* __restrict__ out) {
    __shared__ float tf[10][32];       // [w][i], i<16: amp*fr, i>=16: amp*fi
    __shared__ float contrib[10][32];  // [w][c*2+o]
    __shared__ int   lastflag;
    __shared__ float bnbuf[32][257];   // [q = ch*2+o][b], padded rows

    int b = blockIdx.x;
    int tid = threadIdx.x;

    // ---- phase A: reduce over s, coalesced; idx = (c*10+w)*2+o = tid ----
    if (tid < 320) {
        const float* fp = fpart_g + (size_t)b * 32 * 320 + tid;
        float v = 0.f;
#pragma unroll
        for (int s = 0; s < 32; s++) v += fp[(size_t)s * 320];
        float other = __shfl_xor_sync(0xffffffffu, v, 1);
        float amp = v * v + other * other;
        int pair = tid >> 1;          // c*10 + w
        int o    = tid & 1;
        int c    = pair / 10;
        int w    = pair - c * 10;
        tf[w][c + 16 * o] = amp * v;  // o=0: amp*fr ; o=1: amp*fi
    }
    __syncthreads();

    // ---- phase B: Linear(2C->2) + output-filter weighting ----
    if (tid < 320) {
        int w = tid >> 5;
        int q = tid & 31;
        int c = q >> 1;
        int o = q & 1;
        float acc = 0.f;
        const float* wn = Wnl + (c * 2 + o) * 32;
#pragma unroll
        for (int i = 0; i < 32; i++) acc += tf[w][i] * wn[i];
        float wo = (o == 0 ? WoR : WoI)[c * 10 + w];
        contrib[w][q] = acc * wo;
    }
    __syncthreads();

    // ---- phase C: sum over w, write pre-BN output ----
    if (tid < 32) {
        float ssum = 0.f;
#pragma unroll
        for (int ww = 0; ww < 10; ww++) ssum += contrib[ww][tid];
        out_g[b * 32 + tid] = ssum;
    }
    __threadfence();
    __syncthreads();
    if (tid == 0) lastflag = (atomicAdd(&done_ctr, 1) == 255);
    __syncthreads();
    if (!lastflag) return;

    // ----- last block: BatchNorm over (b, o) per channel -----
    for (int i = tid; i < 8192; i += 512) {
        int bb = i >> 5;
        int q  = i & 31;
        bnbuf[q][bb] = __ldcg(&out_g[i]);
    }
    __syncthreads();

    // one warp per channel
    int ch = tid >> 5, lane = tid & 31;
    {
        float s1 = 0.f;
#pragma unroll
        for (int j = 0; j < 8; j++) {
            int bb = lane + j * 32;
            s1 += bnbuf[2 * ch][bb] + bnbuf[2 * ch + 1][bb];
        }
#pragma unroll
        for (int off = 16; off; off >>= 1) s1 += __shfl_xor_sync(0xffffffffu, s1, off);
        float mean = s1 * (1.f / 512.f);

        float s2 = 0.f;
#pragma unroll
        for (int j = 0; j < 8; j++) {
            int bb = lane + j * 32;
            float d0 = bnbuf[2 * ch][bb] - mean;
            float d1 = bnbuf[2 * ch + 1][bb] - mean;
            s2 += d0 * d0 + d1 * d1;
        }
#pragma unroll
        for (int off = 16; off; off >>= 1) s2 += __shfl_xor_sync(0xffffffffu, s2, off);
        float inv = rsqrtf(s2 * (1.f / 512.f) + 1e-5f);

        float g = gamma[ch], bb_ = beta[ch];
#pragma unroll
        for (int j = 0; j < 8; j++) {
            int bb = lane + j * 32;
            out[bb * 32 + 2 * ch]     = (bnbuf[2 * ch][bb] - mean) * inv * g + bb_;
            out[bb * 32 + 2 * ch + 1] = (bnbuf[2 * ch + 1][bb] - mean) * inv * g + bb_;
        }
    }

    // reset for next graph replay
    if (tid == 0) done_ctr = 0;
}

// ---------------- launch ----------------
extern "C" void kernel_launch(void* const* d_in, const int* in_sizes, int n_in,
                              void* d_out, int out_size) {
    const float* x     = (const float*)d_in[0];
    const float* wir   = (const float*)d_in[1];
    const float* wii   = (const float*)d_in[2];
    const float* wnl   = (const float*)d_in[3];
    const float* wor   = (const float*)d_in[4];
    const float* woi   = (const float*)d_in[5];
    const float* gamma = (const float*)d_in[6];
    const float* beta  = (const float*)d_in[7];
    float* out = (float*)d_out;

    stage1_kernel<<<dim3(16, 32), 256>>>(x, wir, wii);
    stage23_kernel<<<256, 512>>>(wnl, wor, woi, gamma, beta, out);
}